// round 2
// baseline (speedup 1.0000x reference)
#include <cuda_runtime.h>

#define NN 4096
#define DIM 64
#define INF_V 1e10f
#define NBLK 128          // 32 rows per DP block (one warp)
#define CCH 16            // boundary publish granularity (columns)

// Scratch (static __device__ arrays: allocation-free per harness rules)
__device__ float g_D[(size_t)NN * NN];    // 64 MB cost matrix
__device__ float g_xn[NN];
__device__ float g_yn[NN];
__device__ float g_bnd[NBLK][NN];         // bottom boundary row of each block
__device__ int   g_prog[NBLK];            // columns published per block

// ---------------- norms ----------------
__global__ void norms_kernel(const float* __restrict__ x, const float* __restrict__ y) {
    int w = (blockIdx.x * blockDim.x + threadIdx.x) >> 5;
    int lane = threadIdx.x & 31;
    if (w >= 2 * NN) return;
    const float* src = (w < NN) ? x : y;
    int row = (w < NN) ? w : w - NN;
    float a = src[row * DIM + lane];
    float b = src[row * DIM + 32 + lane];
    float s = a * a + b * b;
    #pragma unroll
    for (int o = 16; o; o >>= 1) s += __shfl_xor_sync(0xffffffffu, s, o);
    if (lane == 0) { if (w < NN) g_xn[row] = s; else g_yn[row] = s; }
}

// ---------------- D = |x|^2 + |y|^2 - 2 x.y  (64x64 tile per block) ----------------
__global__ void dmat_kernel(const float* __restrict__ x, const float* __restrict__ y) {
    __shared__ float xs[64][65];
    __shared__ float ys[64][65];
    int tx = threadIdx.x, ty = threadIdx.y;
    int tid = ty * 16 + tx;
    int rb = blockIdx.y * 64, cb = blockIdx.x * 64;

    for (int i = tid; i < 64 * 64; i += 256) {
        int rr = i >> 6, kk = i & 63;
        xs[rr][kk] = x[(rb + rr) * DIM + kk];
        ys[rr][kk] = y[(cb + rr) * DIM + kk];
    }
    __syncthreads();

    float acc[4][4] = {};
    #pragma unroll
    for (int k = 0; k < 64; k++) {
        float xv[4], yv[4];
        #pragma unroll
        for (int i = 0; i < 4; i++) xv[i] = xs[ty + 16 * i][k];
        #pragma unroll
        for (int j = 0; j < 4; j++) yv[j] = ys[tx + 16 * j][k];
        #pragma unroll
        for (int i = 0; i < 4; i++)
            #pragma unroll
            for (int j = 0; j < 4; j++)
                acc[i][j] += xv[i] * yv[j];
    }

    #pragma unroll
    for (int i = 0; i < 4; i++) {
        int r = rb + ty + 16 * i;
        float xnr = g_xn[r];
        #pragma unroll
        for (int j = 0; j < 4; j++) {
            int c = cb + tx + 16 * j;
            g_D[(size_t)r * NN + c] = xnr + g_yn[c] - 2.0f * acc[i][j];
        }
    }
}

// ---------------- reset progress flags (graph replays reuse state) ----------------
__global__ void init_kernel() {
    if (threadIdx.x < NBLK) g_prog[threadIdx.x] = 0;
}

// ---------------- DP wavefront: 1 warp per 32-row band, no barriers ----------------
__device__ __forceinline__ int ld_acq(const int* p) {
    int v;
    asm volatile("ld.acquire.gpu.u32 %0, [%1];" : "=r"(v) : "l"(p) : "memory");
    return v;
}
__device__ __forceinline__ void st_rel(int* p, int v) {
    asm volatile("st.release.gpu.u32 [%0], %1;" :: "l"(p), "r"(v) : "memory");
}

__global__ void __launch_bounds__(32, 1) dp_kernel(float* __restrict__ out) {
    __shared__ float topb[CCH + 1];

    const int b = blockIdx.x;
    const int L = threadIdx.x;               // lane == local row
    const int r = b * 32 + L;
    const float4* __restrict__ Drow4 = (const float4*)(g_D + (size_t)r * NN);
    float* mybnd = g_bnd[b];
    const float* upbnd = (b > 0) ? g_bnd[b - 1] : (const float*)0;

    // D prefetch pipeline: dcur covers quad c/4, dnxt the following quad.
    float4 dcur = __ldg(Drow4 + 0);
    float4 dnxt = __ldg(Drow4 + 1);

    float left = INF_V;      // v[r][c-1]
    float dg   = INF_V;      // v[r-1][c-1]  (== neighbor's up from last step)
    float v    = INF_V;      // this lane's latest value (shfl source)

    const int T = NN + 31;
    #pragma unroll 1
    for (int t = 0; t < T; t++) {
        // Stage a CCH-wide window of the boundary row from the block above.
        if (b > 0 && t < NN && (t & (CCH - 1)) == 0) {
            if (L == 0) {
                int need = t + CCH; if (need > NN) need = NN;
                while (ld_acq(&g_prog[b - 1]) < need) { }
            }
            __syncwarp();
            if (L <= CCH) {
                int col = t - 1 + L;         // window covers cols [t-1, t+CCH-1]
                topb[L] = (col >= 0) ? __ldcg(&upbnd[col]) : INF_V;
            }
            __syncwarp();
        }

        // up = v[r-1][c] : neighbor's value from last step (one shuffle).
        float upv = __shfl_up_sync(0xffffffffu, v, 1);
        const int c = t - L;

        if (L == 0) {
            if (b == 0) { upv = INF_V; dg = (c == 0) ? 0.0f : INF_V; }
            else { int p = t & (CCH - 1); upv = topb[p + 1]; dg = topb[p]; }
        }

        if (c >= 0 && c < NN) {
            int ph = c & 3;
            if (ph == 0 && c > 0) {          // rotate quad, prefetch next
                dcur = dnxt;
                int q = (c >> 2) + 1;
                if (q >= NN / 4) q = NN / 4 - 1;
                dnxt = __ldg(Drow4 + q);
            }
            float cost = (ph == 0) ? dcur.x : (ph == 1) ? dcur.y
                       : (ph == 2) ? dcur.z : dcur.w;

            float m = fminf(fminf(upv, dg), left);
            float s = __expf(m - upv) + __expf(m - dg) + __expf(m - left);
            float nv = cost + m - __logf(s);
            left = nv;
            v = nv;

            if (L == 31 && b < NBLK - 1) {
                mybnd[c] = nv;
                if (((c + 1) & (CCH - 1)) == 0)
                    st_rel(&g_prog[b], c + 1);   // release orders mybnd stores
            }
        } else {
            v = INF_V;                        // inactive lanes feed INF to shfl
        }

        if (L > 0) dg = upv;                  // diag for next step = this step's up
    }

    if (b == NBLK - 1 && L == 31) out[0] = left;   // dp[4096][4096]
}

extern "C" void kernel_launch(void* const* d_in, const int* in_sizes, int n_in,
                              void* d_out, int out_size) {
    const float* x = (const float*)d_in[0];
    const float* y = (const float*)d_in[1];
    float* out = (float*)d_out;

    norms_kernel<<<(2 * NN * 32) / 256, 256>>>(x, y);
    dim3 gD(NN / 64, NN / 64);
    dim3 bD(16, 16);
    dmat_kernel<<<gD, bD>>>(x, y);
    init_kernel<<<1, NBLK>>>();
    dp_kernel<<<NBLK, 32>>>(out);
}

// round 3
// speedup vs baseline: 1.1789x; 1.1789x over previous
#include <cuda_runtime.h>

#define NN 4096
#define NNP 4104          // skewed row stride (mult of 4, +8 pad)
#define DIM 64
#define INF_V 1e10f
#define NBLK 128          // 32 rows per DP block (one warp)

// Scratch (static __device__ arrays: allocation-free per harness rules)
__device__ float g_Ds[(size_t)NN * NNP + 64]; // skewed cost matrix: D[r][c] at [r*NNP + c + (r&3)]
__device__ float g_xn[NN];
__device__ float g_yn[NN];
__device__ float g_bnd[NBLK][NN];             // bottom boundary row of each block
__device__ int   g_prog[NBLK];                // columns published per block

// ---------------- norms ----------------
__global__ void norms_kernel(const float* __restrict__ x, const float* __restrict__ y) {
    int w = (blockIdx.x * blockDim.x + threadIdx.x) >> 5;
    int lane = threadIdx.x & 31;
    if (w >= 2 * NN) return;
    const float* src = (w < NN) ? x : y;
    int row = (w < NN) ? w : w - NN;
    float a = src[row * DIM + lane];
    float b = src[row * DIM + 32 + lane];
    float s = a * a + b * b;
    #pragma unroll
    for (int o = 16; o; o >>= 1) s += __shfl_xor_sync(0xffffffffu, s, o);
    if (lane == 0) { if (w < NN) g_xn[row] = s; else g_yn[row] = s; }
}

// ---------------- D = |x|^2 + |y|^2 - 2 x.y, written row-skewed ----------------
__global__ void dmat_kernel(const float* __restrict__ x, const float* __restrict__ y) {
    __shared__ float xs[64][65];
    __shared__ float ys[64][65];
    int tx = threadIdx.x, ty = threadIdx.y;
    int tid = ty * 16 + tx;
    int rb = blockIdx.y * 64, cb = blockIdx.x * 64;

    for (int i = tid; i < 64 * 64; i += 256) {
        int rr = i >> 6, kk = i & 63;
        xs[rr][kk] = x[(rb + rr) * DIM + kk];
        ys[rr][kk] = y[(cb + rr) * DIM + kk];
    }
    __syncthreads();

    float acc[4][4] = {};
    #pragma unroll
    for (int k = 0; k < 64; k++) {
        float xv[4], yv[4];
        #pragma unroll
        for (int i = 0; i < 4; i++) xv[i] = xs[ty + 16 * i][k];
        #pragma unroll
        for (int j = 0; j < 4; j++) yv[j] = ys[tx + 16 * j][k];
        #pragma unroll
        for (int i = 0; i < 4; i++)
            #pragma unroll
            for (int j = 0; j < 4; j++)
                acc[i][j] += xv[i] * yv[j];
    }

    #pragma unroll
    for (int i = 0; i < 4; i++) {
        int r = rb + ty + 16 * i;
        float xnr = g_xn[r];
        #pragma unroll
        for (int j = 0; j < 4; j++) {
            int c = cb + tx + 16 * j;
            g_Ds[(size_t)r * NNP + c + (r & 3)] = xnr + g_yn[c] - 2.0f * acc[i][j];
        }
    }
}

// ---------------- reset progress flags (graph replays reuse state) ----------------
__global__ void init_kernel() {
    if (threadIdx.x < NBLK) g_prog[threadIdx.x] = 0;
}

// ---------------- DP wavefront ----------------
__device__ __forceinline__ int ld_acq(const int* p) {
    int v;
    asm volatile("ld.acquire.gpu.u32 %0, [%1];" : "=r"(v) : "l"(p) : "memory");
    return v;
}
__device__ __forceinline__ void st_rel(int* p, int v) {
    asm volatile("st.release.gpu.u32 [%0], %1;" :: "l"(p), "r"(v) : "memory");
}

__device__ __forceinline__ float cell(float up_s, float dg_s, float left, float cost) {
    float m = fminf(fminf(up_s, dg_s), left);
    float s = __expf(m - up_s) + __expf(m - dg_s) + __expf(m - left);
    return cost + m - __logf(s);
}

__global__ void __launch_bounds__(32, 1) dp_kernel(float* __restrict__ out) {
    __shared__ float topb[17];     // boundary window: topb[j] = upbnd[t0-1+j]

    const int b = blockIdx.x;
    const int L = threadIdx.x;                 // lane == local row
    const int r = b * 32 + L;
    const float* __restrict__ Drow = g_Ds + (size_t)r * NNP;
    const int woff = 4 * (L >> 2);             // lane stream offset: idx = t - woff
    float* mybnd = g_bnd[b];
    const float* upbnd = (b > 0) ? g_bnd[b - 1] : (const float*)0;

    if (L < 17) topb[L] = INF_V;               // b==0 steady path reads these (dp[-1][*] = INF)
    __syncwarp();

    float left = INF_V, dg = INF_V, v = INF_V;

    // ======== prologue: t = 0..31 (D prefetched to regs; staging per 16) ========
    float P[32];
    #pragma unroll
    for (int t = 0; t < 32; t++) {
        int idx = t - woff; if (idx < 0) idx = 0;
        P[t] = __ldg(&Drow[idx]);
    }
    #pragma unroll
    for (int t = 0; t < 32; t++) {
        if (b > 0 && (t & 15) == 0) {
            if (L == 0) { while (ld_acq(&g_prog[b - 1]) < t + 16) { } }
            __syncwarp();
            if (L < 17) { int col = t - 1 + L; topb[L] = (col >= 0) ? __ldcg(&upbnd[col]) : INF_V; }
            __syncwarp();
        }
        float upsh = __shfl_up_sync(0xffffffffu, v, 1);
        int c = t - L;
        float up_s, dg_s;
        if (L == 0) {
            if (b == 0) { up_s = INF_V; dg_s = (c == 0) ? 0.0f : INF_V; }
            else { int p = t & 15; up_s = topb[p + 1]; dg_s = topb[p]; }
        } else { up_s = upsh; dg_s = dg; }
        if (c >= 0) {
            float nv = cell(up_s, dg_s, left, P[t]);
            left = nv; v = nv;
            if (L == 31) mybnd[c] = nv;        // only t=31 (c=0) fires
        } else v = INF_V;
        dg = upsh;
    }

    // preload first steady window (t0 = 32)
    float Wc[16];
    {
        const float4* rp = (const float4*)Drow;
        int qb = (32 - woff) >> 2;
        #pragma unroll
        for (int q = 0; q < 4; q++) {
            float4 t4 = __ldg(rp + qb + q);
            Wc[4 * q + 0] = t4.x; Wc[4 * q + 1] = t4.y;
            Wc[4 * q + 2] = t4.z; Wc[4 * q + 3] = t4.w;
        }
    }

    // ======== steady: chunks of 16 anti-diagonal steps, branch-free body ========
    #pragma unroll 1
    for (int t0 = 32; t0 <= NN - 16; t0 += 16) {
        if (b > 0) {
            if (L == 0) { while (ld_acq(&g_prog[b - 1]) < t0 + 16) { } }
            __syncwarp();
            if (L < 17) topb[L] = __ldcg(&upbnd[t0 - 1 + L]);
            __syncwarp();
        }
        // prefetch next window (last iter reads pad garbage; never consumed)
        float4 n0, n1, n2, n3;
        {
            const float4* rp = (const float4*)Drow;
            int qb = (t0 + 16 - woff) >> 2;
            n0 = __ldg(rp + qb + 0); n1 = __ldg(rp + qb + 1);
            n2 = __ldg(rp + qb + 2); n3 = __ldg(rp + qb + 3);
        }
        #pragma unroll
        for (int j = 0; j < 16; j++) {
            float upsh = __shfl_up_sync(0xffffffffu, v, 1);
            float up_s = (L == 0) ? topb[j + 1] : upsh;
            float dg_s = (L == 0) ? topb[j] : dg;
            float nv = cell(up_s, dg_s, left, Wc[j]);
            left = nv; v = nv;
            dg = upsh;
            if (L == 31) mybnd[t0 + j - 31] = nv;
        }
        if (L == 31 && b < NBLK - 1) st_rel(&g_prog[b], t0 - 15);
        Wc[0] = n0.x; Wc[1] = n0.y; Wc[2]  = n0.z; Wc[3]  = n0.w;
        Wc[4] = n1.x; Wc[5] = n1.y; Wc[6]  = n1.z; Wc[7]  = n1.w;
        Wc[8] = n2.x; Wc[9] = n2.y; Wc[10] = n2.z; Wc[11] = n2.w;
        Wc[12] = n3.x; Wc[13] = n3.y; Wc[14] = n3.z; Wc[15] = n3.w;
    }

    // ======== epilogue: t = NN..NN+30 (D prefetched to regs) ========
    float E[31];
    #pragma unroll
    for (int tt = 0; tt < 31; tt++)
        E[tt] = __ldg(&Drow[NN + tt - woff]);
    #pragma unroll
    for (int tt = 0; tt < 31; tt++) {
        int t = NN + tt;
        float upsh = __shfl_up_sync(0xffffffffu, v, 1);
        int c = t - L;
        if (c < NN) {
            float nv = cell(upsh, dg, left, E[tt]);
            left = nv; v = nv;
            if (L == 31) mybnd[c] = nv;
        } else v = INF_V;
        dg = upsh;
    }
    if (L == 31 && b < NBLK - 1) st_rel(&g_prog[b], NN);

    if (b == NBLK - 1 && L == 31) out[0] = left;   // dp[4096][4096]
}

extern "C" void kernel_launch(void* const* d_in, const int* in_sizes, int n_in,
                              void* d_out, int out_size) {
    const float* x = (const float*)d_in[0];
    const float* y = (const float*)d_in[1];
    float* out = (float*)d_out;

    norms_kernel<<<(2 * NN * 32) / 256, 256>>>(x, y);
    dim3 gD(NN / 64, NN / 64);
    dim3 bD(16, 16);
    dmat_kernel<<<gD, bD>>>(x, y);
    init_kernel<<<1, NBLK>>>();
    dp_kernel<<<NBLK, 32>>>(out);
}

// round 4
// speedup vs baseline: 2.2479x; 1.9067x over previous
#include <cuda_runtime.h>

#define NN 4096
#define DIM 64
#define INF_V 1e10f
#define NBLK 32           // 128 rows per DP block (one warp, 4 rows/lane)
#define NTILE 1024        // tile-columns (4 cols each)

// Scratch (static __device__ arrays: allocation-free per harness rules)
__device__ float g_D[(size_t)NN * NN];    // 64 MB cost matrix
__device__ float g_xn[NN];
__device__ float g_yn[NN];
__device__ float g_bnd[NBLK][NN];         // bottom boundary row of each block
__device__ int   g_prog[NBLK];            // tiles published per block

// ---------------- norms ----------------
__global__ void norms_kernel(const float* __restrict__ x, const float* __restrict__ y) {
    int w = (blockIdx.x * blockDim.x + threadIdx.x) >> 5;
    int lane = threadIdx.x & 31;
    if (w >= 2 * NN) return;
    const float* src = (w < NN) ? x : y;
    int row = (w < NN) ? w : w - NN;
    float a = src[row * DIM + lane];
    float b = src[row * DIM + 32 + lane];
    float s = a * a + b * b;
    #pragma unroll
    for (int o = 16; o; o >>= 1) s += __shfl_xor_sync(0xffffffffu, s, o);
    if (lane == 0) { if (w < NN) g_xn[row] = s; else g_yn[row] = s; }
}

// ---------------- D = |x|^2 + |y|^2 - 2 x.y  (64x64 tile per block) ----------------
__global__ void dmat_kernel(const float* __restrict__ x, const float* __restrict__ y) {
    __shared__ float xs[64][65];
    __shared__ float ys[64][65];
    int tx = threadIdx.x, ty = threadIdx.y;
    int tid = ty * 16 + tx;
    int rb = blockIdx.y * 64, cb = blockIdx.x * 64;

    for (int i = tid; i < 64 * 64; i += 256) {
        int rr = i >> 6, kk = i & 63;
        xs[rr][kk] = x[(rb + rr) * DIM + kk];
        ys[rr][kk] = y[(cb + rr) * DIM + kk];
    }
    __syncthreads();

    float acc[4][4] = {};
    #pragma unroll
    for (int k = 0; k < 64; k++) {
        float xv[4], yv[4];
        #pragma unroll
        for (int i = 0; i < 4; i++) xv[i] = xs[ty + 16 * i][k];
        #pragma unroll
        for (int j = 0; j < 4; j++) yv[j] = ys[tx + 16 * j][k];
        #pragma unroll
        for (int i = 0; i < 4; i++)
            #pragma unroll
            for (int j = 0; j < 4; j++)
                acc[i][j] += xv[i] * yv[j];
    }

    #pragma unroll
    for (int i = 0; i < 4; i++) {
        int r = rb + ty + 16 * i;
        float xnr = g_xn[r];
        #pragma unroll
        for (int j = 0; j < 4; j++) {
            int c = cb + tx + 16 * j;
            g_D[(size_t)r * NN + c] = xnr + g_yn[c] - 2.0f * acc[i][j];
        }
    }
}

// ---------------- reset progress flags (graph replays reuse state) ----------------
__global__ void init_kernel() {
    if (threadIdx.x < NBLK) g_prog[threadIdx.x] = 0;
}

// ---------------- DP wavefront: 4x4 register tiles, 1 warp per 128-row band ----
__device__ __forceinline__ int ld_acq(const int* p) {
    int v;
    asm volatile("ld.acquire.gpu.u32 %0, [%1];" : "=r"(v) : "l"(p) : "memory");
    return v;
}
__device__ __forceinline__ void st_rel(int* p, int v) {
    asm volatile("st.release.gpu.u32 [%0], %1;" :: "l"(p), "r"(v) : "memory");
}

#define CELL(nv, u, d, l, cost) do {                                   \
    float m_ = fminf(fminf((u), (d)), (l));                            \
    float s_ = __expf(m_ - (u)) + __expf(m_ - (d)) + __expf(m_ - (l)); \
    (nv) = (cost) + m_ - __logf(s_);                                   \
} while (0)

__global__ void __launch_bounds__(32, 1) dp_kernel(float* __restrict__ out) {
    __shared__ float topb[17];   // boundary window: cols [4*tauc-1 .. 4*tauc+15]

    const int b = blockIdx.x;
    const int L = threadIdx.x;
    const int row0 = b * 128 + 4 * L;
    const float4* __restrict__ Dr0 = (const float4*)(g_D + (size_t)(row0 + 0) * NN);
    const float4* __restrict__ Dr1 = (const float4*)(g_D + (size_t)(row0 + 1) * NN);
    const float4* __restrict__ Dr2 = (const float4*)(g_D + (size_t)(row0 + 2) * NN);
    const float4* __restrict__ Dr3 = (const float4*)(g_D + (size_t)(row0 + 3) * NN);
    float* mybnd = g_bnd[b];
    const float* upbnd = (b > 0) ? g_bnd[b - 1] : (const float*)0;

    float lft[4] = {INF_V, INF_V, INF_V, INF_V};  // v[row i][4j-1]
    float bot0 = INF_V, bot1 = INF_V, bot2 = INF_V, bot3 = INF_V; // row3 of last tile
    float dgv = INF_V;                            // v[row0-1][4j-1]

    // prefetch tile 0 costs
    float4 c0 = __ldg(Dr0), c1 = __ldg(Dr1), c2 = __ldg(Dr2), c3 = __ldg(Dr3);

    const int TT = NTILE + 31;
    #pragma unroll 1
    for (int tau = 0; tau < TT; tau++) {
        const int j = tau - L;                    // this lane's tile-column

        // ---- stage boundary window every 4 tiles (lane 0's consumption) ----
        if (b > 0 && tau < NTILE && (tau & 3) == 0) {
            if (L == 0) { while (ld_acq(&g_prog[b - 1]) < tau + 4) { } }
            __syncwarp();
            if (L < 17) {
                int col = 4 * tau - 1 + L;
                topb[L] = (col >= 0) ? __ldcg(&upbnd[col]) : INF_V;
            }
            __syncwarp();
        }

        // ---- prefetch next tile's costs (consumed next iteration) ----
        int jn = j + 1; if (jn < 0) jn = 0; if (jn > NTILE - 1) jn = NTILE - 1;
        float4 p0 = __ldg(Dr0 + jn);
        float4 p1 = __ldg(Dr1 + jn);
        float4 p2 = __ldg(Dr2 + jn);
        float4 p3 = __ldg(Dr3 + jn);

        // ---- top handoff: neighbor's bottom row from previous step ----
        float t0 = __shfl_up_sync(0xffffffffu, bot0, 1);
        float t1 = __shfl_up_sync(0xffffffffu, bot1, 1);
        float t2 = __shfl_up_sync(0xffffffffu, bot2, 1);
        float t3 = __shfl_up_sync(0xffffffffu, bot3, 1);
        if (L == 0) {
            if (b == 0) {
                t0 = t1 = t2 = t3 = INF_V;
                dgv = (tau == 0) ? 0.0f : INF_V;
            } else {
                int p = (tau & 3) * 4;
                dgv = topb[p];
                t0 = topb[p + 1]; t1 = topb[p + 2];
                t2 = topb[p + 3]; t3 = topb[p + 4];
            }
        }
        if (j == 0 && L > 0) dgv = INF_V;         // diag of col 0 is dp[.][-1]

        if (j >= 0 && j < NTILE) {
            float u0 = t0, u1 = t1, u2 = t2, u3 = t3;
            float nl[4];
            {   // row 0
                float d = dgv, l = lft[0], n0, n1, n2, n3;
                CELL(n0, u0, d, l, c0.x); d = u0; l = n0;
                CELL(n1, u1, d, l, c0.y); d = u1; l = n1;
                CELL(n2, u2, d, l, c0.z); d = u2; l = n2;
                CELL(n3, u3, d, l, c0.w);
                nl[0] = n3; u0 = n0; u1 = n1; u2 = n2; u3 = n3;
            }
            {   // row 1 (diag at k=0 is OLD lft[0])
                float d = lft[0], l = lft[1], n0, n1, n2, n3;
                CELL(n0, u0, d, l, c1.x); d = u0; l = n0;
                CELL(n1, u1, d, l, c1.y); d = u1; l = n1;
                CELL(n2, u2, d, l, c1.z); d = u2; l = n2;
                CELL(n3, u3, d, l, c1.w);
                nl[1] = n3; u0 = n0; u1 = n1; u2 = n2; u3 = n3;
            }
            {   // row 2
                float d = lft[1], l = lft[2], n0, n1, n2, n3;
                CELL(n0, u0, d, l, c2.x); d = u0; l = n0;
                CELL(n1, u1, d, l, c2.y); d = u1; l = n1;
                CELL(n2, u2, d, l, c2.z); d = u2; l = n2;
                CELL(n3, u3, d, l, c2.w);
                nl[2] = n3; u0 = n0; u1 = n1; u2 = n2; u3 = n3;
            }
            {   // row 3
                float d = lft[2], l = lft[3], n0, n1, n2, n3;
                CELL(n0, u0, d, l, c3.x); d = u0; l = n0;
                CELL(n1, u1, d, l, c3.y); d = u1; l = n1;
                CELL(n2, u2, d, l, c3.z); d = u2; l = n2;
                CELL(n3, u3, d, l, c3.w);
                nl[3] = n3; u0 = n0; u1 = n1; u2 = n2; u3 = n3;
            }
            lft[0] = nl[0]; lft[1] = nl[1]; lft[2] = nl[2]; lft[3] = nl[3];
            bot0 = u0; bot1 = u1; bot2 = u2; bot3 = u3;

            if (L == 31) {
                *(float4*)&mybnd[4 * j] = make_float4(bot0, bot1, bot2, bot3);
                if ((j & 3) == 3 && b < NBLK - 1)
                    st_rel(&g_prog[b], j + 1);   // release orders mybnd stores
            }
        }
        dgv = t3;                                 // diag for next tile = top[3]

        c0 = p0; c1 = p1; c2 = p2; c3 = p3;       // rotate cost buffers
    }

    if (b == NBLK - 1 && L == 31) out[0] = lft[3];   // dp[4096][4096]
}

extern "C" void kernel_launch(void* const* d_in, const int* in_sizes, int n_in,
                              void* d_out, int out_size) {
    const float* x = (const float*)d_in[0];
    const float* y = (const float*)d_in[1];
    float* out = (float*)d_out;

    norms_kernel<<<(2 * NN * 32) / 256, 256>>>(x, y);
    dim3 gD(NN / 64, NN / 64);
    dim3 bD(16, 16);
    dmat_kernel<<<gD, bD>>>(x, y);
    init_kernel<<<1, NBLK>>>();
    dp_kernel<<<NBLK, 32>>>(out);
}